// round 2
// baseline (speedup 1.0000x reference)
#include <cuda_runtime.h>
#include <cuda_bf16.h>
#include <cstdint>

// ---------------------------------------------------------------------------
// Residual VQ: B=8, T=4096, D=128, NUM_CB=8, K=1024
// N = 32768 rows. Outputs (float32, concatenated):
//   [0, 262144)            codes  [B,T,8]  (int codes stored as float)
//   [262144, 262144+4194304) quantized [B,T,128]
//   [4456448]              commitment loss (scalar)
// ---------------------------------------------------------------------------

#define N_ROWS   32768
#define DIM      128
#define NUM_CB   8
#define KCB      1024
#define M_TILE   128
#define PITCH    132          // floats per row in smem tiles (pad vs 128)
#define PITCH4   33           // float4 pitch
#define N_CTAS   (N_ROWS / M_TILE)   // 256
#define CODES_SZ (N_ROWS * NUM_CB)   // 262144
#define QUANT_SZ (N_ROWS * DIM)      // 4194304

__device__ double g_loss;
__device__ float  g_wnorm[NUM_CB * KCB];   // 8192

// ---------------- helpers ----------------
__device__ __forceinline__ unsigned long long pack2(float lo, float hi) {
    unsigned long long r;
    asm("mov.b64 %0, {%1, %2};" : "=l"(r) : "f"(lo), "f"(hi));
    return r;
}
__device__ __forceinline__ float2 unpack2(unsigned long long v) {
    float2 f;
    asm("mov.b64 {%0, %1}, %2;" : "=f"(f.x), "=f"(f.y) : "l"(v));
    return f;
}
__device__ __forceinline__ void ffma2(unsigned long long& d,
                                      unsigned long long a,
                                      unsigned long long b) {
    asm("fma.rn.f32x2 %0, %1, %2, %0;" : "+l"(d) : "l"(a), "l"(b));
}
__device__ __forceinline__ float f4c(const float4& v, int c) {
    switch (c) { case 0: return v.x; case 1: return v.y; case 2: return v.z; default: return v.w; }
}
__device__ __forceinline__ unsigned sortf(float f) {
    unsigned u = __float_as_uint(f);
    return u ^ (((int)u >> 31) | 0x80000000u);
}
__device__ __forceinline__ void cp_async16(void* sdst, const void* gsrc) {
    unsigned saddr = (unsigned)__cvta_generic_to_shared(sdst);
    asm volatile("cp.async.cg.shared.global [%0], [%1], 16;\n" :: "r"(saddr), "l"(gsrc));
}
__device__ __forceinline__ void cp_commit() {
    asm volatile("cp.async.commit_group;\n");
}
__device__ __forceinline__ void cp_wait1() {
    asm volatile("cp.async.wait_group 1;\n");
}

// ---------------- wnorm precompute + loss zero ----------------
__global__ void wnorm_kernel(const float* __restrict__ cb) {
    int k = blockIdx.x * blockDim.x + threadIdx.x;   // 0..8191
    if (blockIdx.x == 0 && threadIdx.x == 0) g_loss = 0.0;
    if (k >= NUM_CB * KCB) return;
    const float4* p = reinterpret_cast<const float4*>(cb + (size_t)k * DIM);
    float4 s = make_float4(0.f, 0.f, 0.f, 0.f);
#pragma unroll
    for (int i = 0; i < 32; ++i) {
        float4 v = p[i];
        s.x = __fadd_rn(s.x, __fmul_rn(v.x, v.x));
        s.y = __fadd_rn(s.y, __fmul_rn(v.y, v.y));
        s.z = __fadd_rn(s.z, __fmul_rn(v.z, v.z));
        s.w = __fadd_rn(s.w, __fmul_rn(v.w, v.w));
    }
    g_wnorm[k] = __fadd_rn(__fadd_rn(s.x, s.y), __fadd_rn(s.z, s.w));
}

// ---------------- main kernel ----------------
// smem layout (floats):
//   A_s    : 128*132            residual tile, row-major pitch 132
//   B0,B1  : 128*132 each       codebook chunk double buffer
//   rownorm: 128
//   rn_part: 256
//   kbest  : 8*128 ints (after floats)
#define SMEM_FLOATS (3 * M_TILE * PITCH + M_TILE + 2 * M_TILE)
#define SMEM_BYTES  (SMEM_FLOATS * 4 + NUM_CB * M_TILE * 4)

__global__ void __launch_bounds__(256, 1)
rvq_main(const float* __restrict__ emb, const float* __restrict__ cb,
         float* __restrict__ out) {
    extern __shared__ float sm[];
    float* A_s     = sm;
    float* B0      = A_s + M_TILE * PITCH;
    float* B1      = B0 + M_TILE * PITCH;
    float* rownorm = B1 + M_TILE * PITCH;
    float* rn_part = rownorm + M_TILE;
    int*   kbest   = reinterpret_cast<int*>(rn_part + 2 * M_TILE);

    const int tid = threadIdx.x;
    const int tx  = tid & 15;
    const int ty  = tid >> 4;
    const int row0 = blockIdx.x * M_TILE;

    // ---- load A tile (embeddings) ----
    {
        const float4* ev = reinterpret_cast<const float4*>(emb + (size_t)row0 * DIM);
#pragma unroll
        for (int i = 0; i < 16; ++i) {
            int f = tid + i * 256;
            int r = f >> 5, d4 = f & 31;
            reinterpret_cast<float4*>(A_s)[r * PITCH4 + d4] = ev[f];
        }
    }

    // ---- prefetch first B tile ----
    {
        const float* src = cb;   // tile 0 = cb[0], chunk 0
#pragma unroll
        for (int i = 0; i < 16; ++i) {
            int f = tid + i * 256;
            int j = f >> 5, d4 = f & 31;
            cp_async16(B0 + j * PITCH + d4 * 4, src + (size_t)f * 4);
        }
        cp_commit();
    }

    __syncthreads();

    // ---- initial row norms ||e||^2 ----
    {
        int r = tid & 127, h = tid >> 7;
        const float* a = A_s + r * PITCH + h * 64;
        float4 s = make_float4(0.f, 0.f, 0.f, 0.f);
#pragma unroll
        for (int i = 0; i < 16; ++i) {
            float4 v = *reinterpret_cast<const float4*>(a + 4 * i);
            s.x = __fadd_rn(s.x, __fmul_rn(v.x, v.x));
            s.y = __fadd_rn(s.y, __fmul_rn(v.y, v.y));
            s.z = __fadd_rn(s.z, __fmul_rn(v.z, v.z));
            s.w = __fadd_rn(s.w, __fmul_rn(v.w, v.w));
        }
        rn_part[h * 128 + r] = __fadd_rn(__fadd_rn(s.x, s.y), __fadd_rn(s.z, s.w));
    }
    __syncthreads();
    if (tid < 128) rownorm[tid] = __fadd_rn(rn_part[tid], rn_part[128 + tid]);
    __syncthreads();

    double loss_acc = 0.0;
    int g = 0;   // global tile index 0..63

    for (int cbi = 0; cbi < NUM_CB; ++cbi) {
        unsigned long long best[8];
#pragma unroll
        for (int j = 0; j < 8; ++j) best[j] = ~0ull;

        for (int chunk = 0; chunk < 8; ++chunk, ++g) {
            float* Bcur  = (g & 1) ? B1 : B0;
            float* Bnext = (g & 1) ? B0 : B1;

            // prefetch next tile
            if (g + 1 < 64) {
                const float* src = cb + (size_t)(g + 1) * (128 * DIM);
#pragma unroll
                for (int i = 0; i < 16; ++i) {
                    int f = tid + i * 256;
                    int j = f >> 5, d4 = f & 31;
                    cp_async16(Bnext + j * PITCH + d4 * 4, src + (size_t)f * 4);
                }
            }
            cp_commit();
            cp_wait1();
            __syncthreads();

            // per-thread wnorm for its 8 columns
            float wn[8];
#pragma unroll
            for (int i = 0; i < 8; ++i)
                wn[i] = g_wnorm[cbi * KCB + chunk * 128 + tx + 16 * i];

            // ---- GEMM: acc[j][i2] packed f32x2 over column pairs ----
            unsigned long long acc[8][4];
#pragma unroll
            for (int j = 0; j < 8; ++j)
#pragma unroll
                for (int i2 = 0; i2 < 4; ++i2) acc[j][i2] = 0ull;

#pragma unroll 4
            for (int kk4 = 0; kk4 < 32; ++kk4) {
                float4 bv[8];
#pragma unroll
                for (int i = 0; i < 8; ++i)
                    bv[i] = *reinterpret_cast<const float4*>(
                        Bcur + (tx + 16 * i) * PITCH + kk4 * 4);
                unsigned long long b2[4][4];
#pragma unroll
                for (int dk = 0; dk < 4; ++dk)
#pragma unroll
                    for (int i2 = 0; i2 < 4; ++i2)
                        b2[dk][i2] = pack2(f4c(bv[2 * i2], dk), f4c(bv[2 * i2 + 1], dk));
#pragma unroll
                for (int j = 0; j < 8; ++j) {
                    float4 av = *reinterpret_cast<const float4*>(
                        A_s + (ty + 16 * j) * PITCH + kk4 * 4);
#pragma unroll
                    for (int dk = 0; dk < 4; ++dk) {
                        float a = f4c(av, dk);
                        unsigned long long a2 = pack2(a, a);
#pragma unroll
                        for (int i2 = 0; i2 < 4; ++i2)
                            ffma2(acc[j][i2], a2, b2[dk][i2]);
                    }
                }
            }

            // ---- scores + running argmin ----
#pragma unroll
            for (int j = 0; j < 8; ++j) {
                int row = ty + 16 * j;
                float a = rownorm[row];
                unsigned long long m = ~0ull;
#pragma unroll
                for (int i2 = 0; i2 < 4; ++i2) {
                    float2 d = unpack2(acc[j][i2]);
                    int c0 = chunk * 128 + tx + 16 * (2 * i2);
                    int c1 = c0 + 16;
                    float s0 = __fadd_rn(__fadd_rn(a, -2.0f * d.x), wn[2 * i2]);
                    float s1 = __fadd_rn(__fadd_rn(a, -2.0f * d.y), wn[2 * i2 + 1]);
                    unsigned long long k0 = ((unsigned long long)sortf(s0) << 32) | (unsigned)c0;
                    unsigned long long k1 = ((unsigned long long)sortf(s1) << 32) | (unsigned)c1;
                    m = min(m, k0);
                    m = min(m, k1);
                }
#pragma unroll
                for (int off = 1; off < 16; off <<= 1) {
                    unsigned long long o = __shfl_xor_sync(0xffffffffu, m, off);
                    m = min(m, o);
                }
                best[j] = min(best[j], m);
            }
            __syncthreads();   // Bcur safe to overwrite next iteration
        }

        // ---- commit codes + kbest for this codebook ----
        if (tx == 0) {
#pragma unroll
            for (int j = 0; j < 8; ++j) {
                int row = ty + 16 * j;
                int k = (int)(unsigned)best[j];
                kbest[cbi * M_TILE + row] = k;
                out[(size_t)(row0 + row) * NUM_CB + cbi] = (float)k;
            }
        }
        __syncthreads();

        // ---- residual update, new row norms, loss ----
        {
            int r = tid & 127, h = tid >> 7;
            int k = kbest[cbi * M_TILE + r];
            const float* wp = cb + ((size_t)(cbi * KCB + k) * DIM + h * 64);
            float* ap = A_s + r * PITCH + h * 64;
            float4 s = make_float4(0.f, 0.f, 0.f, 0.f);
#pragma unroll
            for (int i = 0; i < 16; ++i) {
                float4 rv = *reinterpret_cast<const float4*>(ap + 4 * i);
                float4 wv = *reinterpret_cast<const float4*>(wp + 4 * i);
                float4 nr;
                nr.x = __fadd_rn(rv.x, -wv.x);
                nr.y = __fadd_rn(rv.y, -wv.y);
                nr.z = __fadd_rn(rv.z, -wv.z);
                nr.w = __fadd_rn(rv.w, -wv.w);
                *reinterpret_cast<float4*>(ap + 4 * i) = nr;
                s.x = __fadd_rn(s.x, __fmul_rn(nr.x, nr.x));
                s.y = __fadd_rn(s.y, __fmul_rn(nr.y, nr.y));
                s.z = __fadd_rn(s.z, __fmul_rn(nr.z, nr.z));
                s.w = __fadd_rn(s.w, __fmul_rn(nr.w, nr.w));
            }
            float p = __fadd_rn(__fadd_rn(s.x, s.y), __fadd_rn(s.z, s.w));
            rn_part[h * 128 + r] = p;
            loss_acc += (double)p;   // loss term = ||r - w||^2 = ||r_new||^2
        }
        __syncthreads();
        if (tid < 128) rownorm[tid] = __fadd_rn(rn_part[tid], rn_part[128 + tid]);
        __syncthreads();
    }

    // ---- quantized output: q = sum_c w_c (in order), out = e + (q - e) ----
    {
        int r = tid & 127, h = tid >> 7;
        int n = row0 + r;
        int ks[NUM_CB];
#pragma unroll
        for (int c = 0; c < NUM_CB; ++c) ks[c] = kbest[c * M_TILE + r];
#pragma unroll 4
        for (int d4 = 0; d4 < 16; ++d4) {
            int d = h * 64 + d4 * 4;
            float4 q = make_float4(0.f, 0.f, 0.f, 0.f);
#pragma unroll
            for (int c = 0; c < NUM_CB; ++c) {
                float4 wv = *reinterpret_cast<const float4*>(
                    cb + (size_t)(c * KCB + ks[c]) * DIM + d);
                q.x = __fadd_rn(q.x, wv.x);
                q.y = __fadd_rn(q.y, wv.y);
                q.z = __fadd_rn(q.z, wv.z);
                q.w = __fadd_rn(q.w, wv.w);
            }
            float4 e = *reinterpret_cast<const float4*>(emb + (size_t)n * DIM + d);
            float4 o;
            o.x = __fadd_rn(e.x, __fadd_rn(q.x, -e.x));
            o.y = __fadd_rn(e.y, __fadd_rn(q.y, -e.y));
            o.z = __fadd_rn(e.z, __fadd_rn(q.z, -e.z));
            o.w = __fadd_rn(e.w, __fadd_rn(q.w, -e.w));
            *reinterpret_cast<float4*>(out + CODES_SZ + (size_t)n * DIM + d) = o;
        }
    }

    // ---- loss reduction ----
    double v = loss_acc;
#pragma unroll
    for (int off = 16; off > 0; off >>= 1)
        v += __shfl_down_sync(0xffffffffu, v, off);
    if ((tid & 31) == 0) atomicAdd(&g_loss, v);
}

__global__ void finalize_kernel(float* __restrict__ out) {
    out[CODES_SZ + QUANT_SZ] = (float)(g_loss / ((double)QUANT_SZ * (double)NUM_CB));
}

// ---------------------------------------------------------------------------
extern "C" void kernel_launch(void* const* d_in, const int* in_sizes, int n_in,
                              void* d_out, int out_size) {
    const float* emb = (const float*)d_in[0];   // [8,4096,128]
    const float* cb  = (const float*)d_in[1];   // [8,1024,128]
    float* out = (float*)d_out;

    cudaFuncSetAttribute(rvq_main, cudaFuncAttributeMaxDynamicSharedMemorySize,
                         SMEM_BYTES);

    wnorm_kernel<<<32, 256>>>(cb);
    rvq_main<<<N_CTAS, 256, SMEM_BYTES>>>(emb, cb, out);
    finalize_kernel<<<1, 1>>>(out);
}

// round 9
// speedup vs baseline: 1.4585x; 1.4585x over previous
#include <cuda_runtime.h>
#include <cuda_bf16.h>
#include <cstdint>

// ---------------------------------------------------------------------------
// Residual VQ: B=8, T=4096, D=128, NUM_CB=8, K=1024   (N = 32768 rows)
// out (float32): [0,262144) codes [B,T,8]; [262144,+4194304) quantized; last = loss
//
// FFMA2 (fma.rn.f32x2) v2:
//  - W pre-paired in global: g_wp[tile][k][64 pairs] (float2) -> b operand is a
//    single LDS.64, already packed for f32x2 FMA (no pack MOVs for B).
//  - 512 threads / 16 warps (4 per SMSP) for latency hiding; per-thread tile
//    4 rows x 4 col-pairs (16 u64 accumulators).
//  - dot accumulation chain bitwise-identical to the proven R1 kernel
//    (k ascending, fused FFMA2), same score/argmin/residual/loss epilogue.
// ---------------------------------------------------------------------------

#define N_ROWS   32768
#define DIM      128
#define NUM_CB   8
#define KCB      1024
#define M_TILE   128
#define APITCH   132                   // A row pitch (floats)
#define N_CTAS   (N_ROWS / M_TILE)     // 256
#define CODES_SZ (N_ROWS * NUM_CB)     // 262144
#define QUANT_SZ (N_ROWS * DIM)        // 4194304
#define THREADS  512
#define CHUNK    128                   // codes per chunk
#define PAIRS    64                    // col pairs per chunk
#define CHUNKS_PER_CB 8
#define TILES    (NUM_CB * CHUNKS_PER_CB)   // 64
#define BTILE_FLOATS (DIM * CHUNK)     // 16384 floats = 64KB

// smem layout (floats)
#define SMF_A    0                                  // 128*132 = 16896
#define SMF_B0   (SMF_A + M_TILE * APITCH)          // 16384
#define SMF_B1   (SMF_B0 + BTILE_FLOATS)            // 16384
#define SMF_WN   (SMF_B1 + BTILE_FLOATS)            // 1024
#define SMF_RN   (SMF_WN + KCB)                     // 128  rownorm
#define SMF_RP   (SMF_RN + M_TILE)                  // 512  rn_part (4 quarters)
#define SMF_KB   (SMF_RP + 4 * M_TILE)              // 1024 ints (kbest 8x128)
#define SMEM_FLOATS (SMF_KB + NUM_CB * M_TILE)
#define SMEM_BYTES  (SMEM_FLOATS * 4)               // 209408

__device__ double g_loss;
__device__ float  g_wnorm[NUM_CB * KCB];                       // 32KB
__device__ __align__(16) float2 g_wp[TILES * DIM * PAIRS];     // 4MB

// ---------------- helpers ----------------
__device__ __forceinline__ unsigned long long pack2(float lo, float hi) {
    unsigned long long r;
    asm("mov.b64 %0, {%1, %2};" : "=l"(r) : "f"(lo), "f"(hi));
    return r;
}
__device__ __forceinline__ float2 unpack2(unsigned long long v) {
    float2 f;
    asm("mov.b64 {%0, %1}, %2;" : "=f"(f.x), "=f"(f.y) : "l"(v));
    return f;
}
__device__ __forceinline__ void ffma2(unsigned long long& d,
                                      unsigned long long a,
                                      unsigned long long b) {
    asm("fma.rn.f32x2 %0, %1, %2, %0;" : "+l"(d) : "l"(a), "l"(b));
}
__device__ __forceinline__ float f4c(const float4& v, int c) {
    switch (c) { case 0: return v.x; case 1: return v.y; case 2: return v.z; default: return v.w; }
}
__device__ __forceinline__ unsigned sortf(float f) {
    unsigned u = __float_as_uint(f);
    return u ^ (((int)u >> 31) | 0x80000000u);
}
__device__ __forceinline__ void cp_async16(void* sdst, const void* gsrc) {
    unsigned saddr = (unsigned)__cvta_generic_to_shared(sdst);
    asm volatile("cp.async.cg.shared.global [%0], [%1], 16;\n" :: "r"(saddr), "l"(gsrc));
}
__device__ __forceinline__ void cp_commit() {
    asm volatile("cp.async.commit_group;\n");
}
__device__ __forceinline__ void cp_wait1() {
    asm volatile("cp.async.wait_group 1;\n");
}

// ---------------- precompute: wnorm + loss zero ----------------
__global__ void wnorm_kernel(const float* __restrict__ cb) {
    int k = blockIdx.x * blockDim.x + threadIdx.x;   // 0..8191
    if (blockIdx.x == 0 && threadIdx.x == 0) g_loss = 0.0;
    if (k >= NUM_CB * KCB) return;
    const float4* p = reinterpret_cast<const float4*>(cb + (size_t)k * DIM);
    float4 s = make_float4(0.f, 0.f, 0.f, 0.f);
#pragma unroll
    for (int i = 0; i < 32; ++i) {
        float4 v = p[i];
        s.x = __fadd_rn(s.x, __fmul_rn(v.x, v.x));
        s.y = __fadd_rn(s.y, __fmul_rn(v.y, v.y));
        s.z = __fadd_rn(s.z, __fmul_rn(v.z, v.z));
        s.w = __fadd_rn(s.w, __fmul_rn(v.w, v.w));
    }
    g_wnorm[k] = __fadd_rn(__fadd_rn(s.x, s.y), __fadd_rn(s.z, s.w));
}

// ---------------- precompute: paired W layout ----------------
// g_wp[g][k][p] = (cb[cbi, chunk*128+2p, k], cb[cbi, chunk*128+2p+1, k])
__global__ void wpair_kernel(const float* __restrict__ cb) {
    int idx = blockIdx.x * 256 + threadIdx.x;      // 0..524287
    int g   = idx >> 13;                           // tile = cbi*8+chunk
    int rem = idx & 8191;
    int k   = rem >> 6;                            // 0..127
    int p   = rem & 63;                            // 0..63
    int cbi = g >> 3, chunk = g & 7;
    int code0 = chunk * CHUNK + 2 * p;
    const float* base = cb + ((size_t)(cbi * KCB + code0)) * DIM + k;
    float2 v;
    v.x = base[0];
    v.y = base[DIM];
    g_wp[idx] = v;
}

// ---------------- main kernel ----------------
__global__ void __launch_bounds__(THREADS, 1)
rvq_main(const float* __restrict__ emb, const float* __restrict__ cb,
         float* __restrict__ out) {
    extern __shared__ float sm[];
    float* A_s     = sm + SMF_A;
    float* B0      = sm + SMF_B0;
    float* B1      = sm + SMF_B1;
    float* WN      = sm + SMF_WN;
    float* rownorm = sm + SMF_RN;
    float* rn_part = sm + SMF_RP;
    int*   kbest   = reinterpret_cast<int*>(sm + SMF_KB);

    const int tid = threadIdx.x;
    const int tx  = tid & 15;          // col-pair group
    const int ty  = tid >> 4;          // 0..31 row group
    const int row0 = blockIdx.x * M_TILE;

    // ---- load A tile (embeddings), pitch 132 ----
    {
        const float4* ev = reinterpret_cast<const float4*>(emb + (size_t)row0 * DIM);
#pragma unroll
        for (int i = 0; i < 8; ++i) {
            int f = tid + i * THREADS;
            int r = f >> 5, d4 = f & 31;
            reinterpret_cast<float4*>(A_s)[r * (APITCH / 4) + d4] = ev[f];
        }
    }

    // ---- prefetch first B tile (paired layout, linear 64KB) ----
    {
        const char* src = reinterpret_cast<const char*>(g_wp);
#pragma unroll
        for (int i = 0; i < 8; ++i) {
            int f = tid + i * THREADS;           // 16B unit, 4096 total
            cp_async16(reinterpret_cast<char*>(B0) + (size_t)f * 16,
                       src + (size_t)f * 16);
        }
        cp_commit();
    }
    __syncthreads();

    // ---- initial row norms ||e||^2 (quarter partials) ----
    {
        int r = tid & 127, h = tid >> 7;         // h = 0..3
        const float4* a = reinterpret_cast<const float4*>(A_s + r * APITCH + h * 32);
        float4 s = make_float4(0.f, 0.f, 0.f, 0.f);
#pragma unroll
        for (int i = 0; i < 8; ++i) {
            float4 v = a[i];
            s.x = __fadd_rn(s.x, __fmul_rn(v.x, v.x));
            s.y = __fadd_rn(s.y, __fmul_rn(v.y, v.y));
            s.z = __fadd_rn(s.z, __fmul_rn(v.z, v.z));
            s.w = __fadd_rn(s.w, __fmul_rn(v.w, v.w));
        }
        rn_part[h * 128 + r] = __fadd_rn(__fadd_rn(s.x, s.y), __fadd_rn(s.z, s.w));
    }
    __syncthreads();
    if (tid < 128)
        rownorm[tid] = __fadd_rn(__fadd_rn(rn_part[tid], rn_part[128 + tid]),
                                 __fadd_rn(rn_part[256 + tid], rn_part[384 + tid]));
    __syncthreads();

    double loss_acc = 0.0;
    int g = 0;   // global tile index 0..63

    for (int cbi = 0; cbi < NUM_CB; ++cbi) {
        // wn for this codebook into smem (1024 floats)
        {
            int f = tid;
            reinterpret_cast<float2*>(WN)[f] =
                reinterpret_cast<const float2*>(g_wnorm + cbi * KCB)[f];
        }
        __syncthreads();

        unsigned long long best[4];
#pragma unroll
        for (int j = 0; j < 4; ++j) best[j] = ~0ull;

        for (int chunk = 0; chunk < CHUNKS_PER_CB; ++chunk, ++g) {
            float* Bcur  = (g & 1) ? B1 : B0;
            float* Bnext = (g & 1) ? B0 : B1;

            // prefetch next tile
            if (g + 1 < TILES) {
                const char* src = reinterpret_cast<const char*>(g_wp)
                                + (size_t)(g + 1) * (BTILE_FLOATS * 4);
#pragma unroll
                for (int i = 0; i < 8; ++i) {
                    int f = tid + i * THREADS;
                    cp_async16(reinterpret_cast<char*>(Bnext) + (size_t)f * 16,
                               src + (size_t)f * 16);
                }
            }
            cp_commit();
            cp_wait1();
            __syncthreads();

            // ---- GEMM: acc[j][i2] packed f32x2 over adjacent column pairs ----
            unsigned long long acc[4][4];
#pragma unroll
            for (int j = 0; j < 4; ++j)
#pragma unroll
                for (int i2 = 0; i2 < 4; ++i2) acc[j][i2] = 0ull;

            const float* a0 = A_s + ty * APITCH;

#pragma unroll 4
            for (int kk4 = 0; kk4 < 32; ++kk4) {
                float4 av[4];
#pragma unroll
                for (int j = 0; j < 4; ++j)
                    av[j] = *reinterpret_cast<const float4*>(
                        a0 + j * (32 * APITCH) + kk4 * 4);
#pragma unroll
                for (int dk = 0; dk < 4; ++dk) {
                    const unsigned long long* brow =
                        reinterpret_cast<const unsigned long long*>(
                            Bcur + (kk4 * 4 + dk) * CHUNK);
                    unsigned long long b2[4];
#pragma unroll
                    for (int i2 = 0; i2 < 4; ++i2)
                        b2[i2] = brow[tx + 16 * i2];
#pragma unroll
                    for (int j = 0; j < 4; ++j) {
                        float a = f4c(av[j], dk);
                        unsigned long long a2 = pack2(a, a);
#pragma unroll
                        for (int i2 = 0; i2 < 4; ++i2)
                            ffma2(acc[j][i2], a2, b2[i2]);
                    }
                }
            }

            // ---- scores + running argmin ----
#pragma unroll
            for (int j = 0; j < 4; ++j) {
                int row = ty + 32 * j;
                float a = rownorm[row];
                unsigned long long m = ~0ull;
#pragma unroll
                for (int i2 = 0; i2 < 4; ++i2) {
                    float2 d = unpack2(acc[j][i2]);
                    int p = tx + 16 * i2;
                    int c0 = chunk * CHUNK + 2 * p;
                    float2 w2 = *reinterpret_cast<const float2*>(WN + c0);
                    float s0 = __fadd_rn(__fadd_rn(a, -2.0f * d.x), w2.x);
                    float s1 = __fadd_rn(__fadd_rn(a, -2.0f * d.y), w2.y);
                    unsigned long long k0 = ((unsigned long long)sortf(s0) << 32) | (unsigned)c0;
                    unsigned long long k1 = ((unsigned long long)sortf(s1) << 32) | (unsigned)(c0 + 1);
                    m = min(m, k0);
                    m = min(m, k1);
                }
#pragma unroll
                for (int off = 1; off < 16; off <<= 1) {
                    unsigned long long o = __shfl_xor_sync(0xffffffffu, m, off);
                    m = min(m, o);
                }
                best[j] = min(best[j], m);
            }
            __syncthreads();   // Bcur safe to overwrite next iteration
        }

        // ---- commit codes + kbest ----
        if (tx == 0) {
#pragma unroll
            for (int j = 0; j < 4; ++j) {
                int row = ty + 32 * j;
                int k = (int)(unsigned)best[j];
                kbest[cbi * M_TILE + row] = k;
                out[(size_t)(row0 + row) * NUM_CB + cbi] = (float)k;
            }
        }
        __syncthreads();

        // ---- residual update (quarters), new row norms, loss ----
        {
            int r = tid & 127, h = tid >> 7;
            int k = kbest[cbi * M_TILE + r];
            const float4* wp = reinterpret_cast<const float4*>(
                cb + ((size_t)(cbi * KCB + k)) * DIM + h * 32);
            float4* ap = reinterpret_cast<float4*>(A_s + r * APITCH + h * 32);
            float4 s = make_float4(0.f, 0.f, 0.f, 0.f);
#pragma unroll
            for (int i = 0; i < 8; ++i) {
                float4 rv = ap[i], wv = wp[i], nr;
                nr.x = __fadd_rn(rv.x, -wv.x);
                nr.y = __fadd_rn(rv.y, -wv.y);
                nr.z = __fadd_rn(rv.z, -wv.z);
                nr.w = __fadd_rn(rv.w, -wv.w);
                ap[i] = nr;
                s.x = __fadd_rn(s.x, __fmul_rn(nr.x, nr.x));
                s.y = __fadd_rn(s.y, __fmul_rn(nr.y, nr.y));
                s.z = __fadd_rn(s.z, __fmul_rn(nr.z, nr.z));
                s.w = __fadd_rn(s.w, __fmul_rn(nr.w, nr.w));
            }
            float p = __fadd_rn(__fadd_rn(s.x, s.y), __fadd_rn(s.z, s.w));
            rn_part[h * 128 + r] = p;
            loss_acc += (double)p;   // loss term = ||r - w||^2 = ||r_new||^2
        }
        __syncthreads();
        if (tid < 128)
            rownorm[tid] = __fadd_rn(__fadd_rn(rn_part[tid], rn_part[128 + tid]),
                                     __fadd_rn(rn_part[256 + tid], rn_part[384 + tid]));
        __syncthreads();
    }

    // ---- quantized output: q = sum_c w_c (in order), out = e + (q - e) ----
    {
        int r = tid & 127, h = tid >> 7;
        int n = row0 + r;
        int ks[NUM_CB];
#pragma unroll
        for (int c = 0; c < NUM_CB; ++c) ks[c] = kbest[c * M_TILE + r];
#pragma unroll
        for (int i = 0; i < 8; ++i) {
            int d4 = h * 8 + i;
            float4 q = make_float4(0.f, 0.f, 0.f, 0.f);
#pragma unroll
            for (int c = 0; c < NUM_CB; ++c) {
                float4 wv = reinterpret_cast<const float4*>(
                    cb + (size_t)(c * KCB + ks[c]) * DIM)[d4];
                q.x = __fadd_rn(q.x, wv.x);
                q.y = __fadd_rn(q.y, wv.y);
                q.z = __fadd_rn(q.z, wv.z);
                q.w = __fadd_rn(q.w, wv.w);
            }
            float4 e = reinterpret_cast<const float4*>(emb + (size_t)n * DIM)[d4];
            float4 o;
            o.x = __fadd_rn(e.x, __fadd_rn(q.x, -e.x));
            o.y = __fadd_rn(e.y, __fadd_rn(q.y, -e.y));
            o.z = __fadd_rn(e.z, __fadd_rn(q.z, -e.z));
            o.w = __fadd_rn(e.w, __fadd_rn(q.w, -e.w));
            reinterpret_cast<float4*>(out + CODES_SZ + (size_t)n * DIM)[d4] = o;
        }
    }

    // ---- loss reduction ----
    double v = loss_acc;
#pragma unroll
    for (int off = 16; off > 0; off >>= 1)
        v += __shfl_down_sync(0xffffffffu, v, off);
    if ((tid & 31) == 0) atomicAdd(&g_loss, v);
}

__global__ void finalize_kernel(float* __restrict__ out) {
    out[CODES_SZ + QUANT_SZ] = (float)(g_loss / ((double)QUANT_SZ * (double)NUM_CB));
}

// ---------------------------------------------------------------------------
extern "C" void kernel_launch(void* const* d_in, const int* in_sizes, int n_in,
                              void* d_out, int out_size) {
    const float* emb = (const float*)d_in[0];   // [8,4096,128]
    const float* cb  = (const float*)d_in[1];   // [8,1024,128]
    float* out = (float*)d_out;

    cudaFuncSetAttribute(rvq_main, cudaFuncAttributeMaxDynamicSharedMemorySize,
                         SMEM_BYTES);

    wnorm_kernel<<<32, 256>>>(cb);
    wpair_kernel<<<2048, 256>>>(cb);
    rvq_main<<<N_CTAS, THREADS, SMEM_BYTES>>>(emb, cb, out);
    finalize_kernel<<<1, 1>>>(out);
}